// round 14
// baseline (speedup 1.0000x reference)
#include <cuda_runtime.h>
#include <math.h>

#define NG 512
#define IMG_H 256
#define IMG_W 256
#define NPIX (IMG_H * IMG_W)
#define EPSV 1e-4f
#define CUT 40.0f

#define NBLK_PROJ 8
#define NBLK_REND 256           // 8 x 32 tiles of 32x8 px, one block per tile
#define NBLK_TOT  (NBLK_PROJ + NBLK_REND)
#define NREADY 64               // fan-out release lines

// Sorted-by-depth gaussian params:
//  g_cull[r] = (mx, my, rx, ry)   conservative ellipse AABB half-extents
//  g_p0[r]   = (mx, my, ia, ib)   mean + inverse-cov entries
//  g_p1[r]   = (id, coeff, colR, colG)
//  g_cb[r]   = colB
__device__ float4 g_cull[NG];
__device__ float4 g_p0[NG];
__device__ float4 g_p1[NG];
__device__ float  g_cb[NG];
// Sync state. Everything returns to 0 before kernel end (graph-replay safe):
//  g_flag1: projection-done counter (0 -> 8)
//  g_ready: 64 fan-out release lines (0 -> 1), polled by render blocks
//  g_fin:   finished-render-block counter (0 -> 256; last block resets all)
__device__ int g_flag1;
__device__ int g_ready[NREADY];
__device__ int g_fin;

__device__ __forceinline__ int acq_load(const int* p) {
    int v;
    asm volatile("ld.acquire.gpu.b32 %0, [%1];" : "=r"(v) : "l"(p) : "memory");
    return v;
}

// ---------------------------------------------------------------------------
// Fused kernel, 264 blocks x 512 threads.
// Residency: launch_bounds(512,2) -> <=64 regs -> occ = min(2048/512,
// 64K/(512*64), smem) = 2 blocks/SM -> 296 slots >= 264 blocks, so ALL
// blocks are co-resident in wave 1 and the ready-line spin cannot deadlock.
//   blocks [0,8):    projection + stable depth sort (8-lane group / gaussian)
//   blocks [8,264):  one block per 32x8 tile: cull+compact all 512 gaussians,
//                    4 warp-groups composite the 4 rank-quarters in parallel,
//                    merge in SMEM (no global partials, fences, or atomics).
// Segment boundaries are ranks 128/256/384 == previous NSEG=4 split, so the
// arithmetic (and rel_err) is identical to R13.
// ---------------------------------------------------------------------------
__global__ void __launch_bounds__(512, 2) fused_kernel(
        const float* __restrict__ means3D,
        const float* __restrict__ covs3d,
        const float* __restrict__ colors,
        const float* __restrict__ opac,
        const float* __restrict__ Km,
        const float* __restrict__ Rm,
        const float* __restrict__ tv,
        float* __restrict__ out) {
    __shared__ __align__(16) unsigned long long skey[NG];   // projection path
    __shared__ float4 sG1[NG + 1];                           // compacted list
    __shared__ float4 sG2[NG + 1];                           // (+1 sentinel)
    __shared__ float  sCB[NG + 1];
    __shared__ float4 sPart[4][256];                         // per-group RGBT
    __shared__ int segTot[16];
    __shared__ int segOff[16];
    __shared__ int sCount;
    __shared__ int sLast;

    int bid  = blockIdx.x;
    int tid  = threadIdx.x;
    int lane = tid & 31;
    int wrp  = tid >> 5;

    // ======================= PROJECTION BLOCKS =============================
    if (bid < NBLK_PROJ) {
        float R00=Rm[0],R01=Rm[1],R02=Rm[2];
        float R10=Rm[3],R11=Rm[4],R12=Rm[5];
        float R20=Rm[6],R21=Rm[7],R22=Rm[8];
        float tx0=tv[0], tx1=tv[1], tx2=tv[2];

        // phase A: all 512 depth keys (1 per thread).
        // depth >= 1 > 0 so float bit order == value order;
        // (depth_bits<<32 | idx) rank == stable jnp.argsort.
        {
            float m0 = means3D[3*tid], m1 = means3D[3*tid+1], m2 = means3D[3*tid+2];
            float cz = R20*m0 + R21*m1 + R22*m2 + tx2;
            float depth = fmaxf(cz, 1.0f);
            skey[tid] = ((unsigned long long)__float_as_uint(depth) << 32) | (unsigned)tid;
        }
        __syncthreads();

        // phase B: each warp owns 4 gaussians via 8-lane groups; all 8 lanes
        // redundantly project (LDG latency overlaps the rank scan below).
        int q   = lane >> 3;       // gaussian within warp (0..3)
        int sub = lane & 7;        // lane within 8-lane group
        int i   = bid * 64 + wrp * 4 + q;

        float m0 = means3D[3*i], m1 = means3D[3*i+1], m2 = means3D[3*i+2];
        const float* C = covs3d + 9*i;
        float C0=C[0],C1=C[1],C2=C[2],C3=C[3],C4=C[4],C5=C[5],C6=C[6],C7=C[7],C8=C[8];
        float c0 = colors[3*i], c1 = colors[3*i+1], c2 = colors[3*i+2];
        float op = opac[i];

        float cx = R00*m0 + R01*m1 + R02*m2 + tx0;
        float cy = R10*m0 + R11*m1 + R12*m2 + tx1;
        float cz = R20*m0 + R21*m1 + R22*m2 + tx2;
        float z = cz;
        float depth = fmaxf(z, 1.0f);

        float K00=Km[0],K01=Km[1],K02=Km[2];
        float K10=Km[3],K11=Km[4],K12=Km[5];
        float K20=Km[6],K21=Km[7],K22=Km[8];

        float sx = K00*cx + K01*cy + K02*cz;
        float sy = K10*cx + K11*cy + K12*cz;
        float sz = K20*cx + K21*cy + K22*cz;
        float mx = sx / sz;
        float my = sy / sz;

        // C_cam = R C R^T ; need (0,0), (0,1), (1,1)
        float u0 = R00*C0 + R01*C3 + R02*C6;
        float u1 = R00*C1 + R01*C4 + R02*C7;
        float u2 = R00*C2 + R01*C5 + R02*C8;
        float v0 = R10*C0 + R11*C3 + R12*C6;
        float v1 = R10*C1 + R11*C4 + R12*C7;
        float v2 = R10*C2 + R11*C5 + R12*C8;
        float Cc00 = u0*R00 + u1*R01 + u2*R02;
        float Cc01 = u0*R10 + u1*R11 + u2*R12;
        float Cc11 = v0*R10 + v1*R11 + v2*R12;

        // only J[0,0]=fx/z, J[1,1]=fy/z survive the [:2,:2] slice of J^T C J
        float jx = K00 / z;
        float jy = K11 / z;
        float a = jx*jx*Cc00 + EPSV;
        float b = jx*jy*Cc01;
        float d = jy*jy*Cc11 + EPSV;

        float det    = a*d - b*b;
        float invdet = 1.0f / det;
        float ia =  d * invdet;
        float ib = -b * invdet;
        float id =  a * invdet;

        float norm  = 1.0f / (6.283185307179586f * sqrtf(det));
        bool  valid = (depth > 1.0f) && (depth < 50.0f);
        float coeff = valid ? (op * norm) : 0.0f;

        float rxv = valid ? sqrtf(CUT * a) : -1e30f;
        float ryv = valid ? sqrtf(CUT * d) : -1e30f;

        // stable rank over ALL 512 keys: 8 lanes x 32 uint4 = 256 uint4.
        unsigned long long ki = skey[i];
        const uint4* sk4 = (const uint4*)skey;
        int r = 0;
        #pragma unroll
        for (int j = 0; j < 32; j++) {
            uint4 v = sk4[sub * 32 + j];
            unsigned long long k0 = ((unsigned long long)v.y << 32) | v.x;
            unsigned long long k1 = ((unsigned long long)v.w << 32) | v.z;
            r += (int)(k0 < ki) + (int)(k1 < ki);
        }
        r += __shfl_down_sync(0xffffffffu, r, 4, 8);
        r += __shfl_down_sync(0xffffffffu, r, 2, 8);
        r += __shfl_down_sync(0xffffffffu, r, 1, 8);

        if (sub == 0) {
            g_cull[r] = make_float4(mx, my, rxv, ryv);
            g_p0[r]   = make_float4(mx, my, ia, ib);
            g_p1[r]   = make_float4(id, coeff, c0, c1);
            g_cb[r]   = c2;
        }
        __syncthreads();
        if (tid == 0) {
            __threadfence();                 // release g_* writes
            sLast = (atomicAdd(&g_flag1, 1) == NBLK_PROJ - 1);
        }
        __syncthreads();
        if (sLast) {
            __threadfence();
            if (tid < NREADY) atomicExch(&g_ready[tid], 1);   // fan-out release
        }
        return;
    }

    // ========================= RENDER BLOCKS (1 per tile) ==================
    int rid = bid - NBLK_PROJ;
    int txi = rid & 7;                   // tile x (0..7)
    int tyi = rid >> 3;                  // tile y (0..31)

    // wait for projection on this block's ready line (4 pollers per line)
    if (tid == 0) {
        while (acq_load(&g_ready[rid & (NREADY - 1)]) == 0) __nanosleep(100);
    }
    __syncthreads();

    float x0 = (float)(txi * 32);
    float y0 = (float)(tyi * 8);
    float x1 = x0 + 31.0f;
    float y1 = y0 + 7.0f;

    // cull all 512 gaussians (1 per thread) against the tile AABB
    float4 c = g_cull[tid];
    bool keep = (c.x + c.z >= x0) && (c.x - c.z <= x1) &&
                (c.y + c.w >= y0) && (c.y - c.w <= y1);
    unsigned mask = __ballot_sync(0xffffffffu, keep);
    if (lane == 0) segTot[wrp] = __popc(mask);
    __syncthreads();

    // exclusive scan over 16 warp totals -> order-preserving offsets;
    // segOff[4g] are exactly the rank-128 boundaries (same split as NSEG=4)
    if (tid < 16) {
        int v = segTot[tid];
        int s = v;
        #pragma unroll
        for (int dd = 1; dd < 16; dd <<= 1) {
            int n = __shfl_up_sync(0x0000ffffu, s, dd);
            if (tid >= dd) s += n;
        }
        segOff[tid] = s - v;
        if (tid == 15) {
            sCount = s;
            // sentinel: far mean, zero coeff -> never hits, kills the clamp
            sG1[s] = make_float4(1e30f, 1e30f, 1.0f, 0.0f);
            sG2[s] = make_float4(1.0f, 0.0f, 0.0f, 0.0f);
            sCB[s] = 0.0f;
        }
    }
    __syncthreads();

    // order-preserving scatter into smem
    if (keep) {
        int pos = segOff[wrp] + __popc(mask & ((1u << lane) - 1u));
        sG1[pos] = g_p0[tid];
        sG2[pos] = g_p1[tid];
        sCB[pos] = g_cb[tid];
    }
    __syncthreads();

    // composite: group g (128 threads) handles rank-quarter g
    int grp  = tid >> 7;                 // 0..3
    int gt   = tid & 127;
    int glane = gt & 31;
    int gw    = gt >> 5;                 // 0..3 (rows gw and gw+4)

    int beg = segOff[grp * 4];
    int end = (grp < 3) ? segOff[grp * 4 + 4] : sCount;

    float T0 = 1.0f, T1 = 1.0f;
    float aR0 = 0.f, aG0 = 0.f, aB0 = 0.f;
    float aR1 = 0.f, aG1 = 0.f, aB1 = 0.f;

    if (beg < end) {
        float px  = x0 + (float)glane;
        float py0 = y0 + (float)gw;
        float py1 = py0 + 4.0f;

        // software-pipelined loop: prefetch i+1 (sentinel-padded, no clamp;
        // for grp<3 the "sentinel" is the next group's first entry — loaded
        // on the last iteration but never used)
        float4 p0 = sG1[beg], p1 = sG2[beg];
        float  cb = sCB[beg];

        for (int i = beg; i < end; i++) {
            float4 n0 = sG1[i + 1];
            float4 n1 = sG2[i + 1];
            float  ncb = sCB[i + 1];

            float dx  = px  - p0.x;
            float dy0 = py0 - p0.y;
            float dy1 = py1 - p0.y;
            float tx  = fmaf(p0.z, dx, p0.w * dy0);
            float ty  = fmaf(p0.w, dx, p1.x * dy0);
            float m0  = fmaf(tx, dx, ty * dy0);
            float ux  = fmaf(p0.z, dx, p0.w * dy1);
            float uy  = fmaf(p0.w, dx, p1.x * dy1);
            float m1  = fmaf(ux, dx, uy * dy1);

            if (fminf(m0, m1) < CUT) {
                float e0 = p1.y * __expf(-0.5f * m0);
                float e1 = p1.y * __expf(-0.5f * m1);
                float w0 = e0 * T0;
                float w1 = e1 * T1;
                aR0 = fmaf(w0, p1.z, aR0);
                aG0 = fmaf(w0, p1.w, aG0);
                aB0 = fmaf(w0, cb,   aB0);
                aR1 = fmaf(w1, p1.z, aR1);
                aG1 = fmaf(w1, p1.w, aG1);
                aB1 = fmaf(w1, cb,   aB1);
                T0 -= w0;
                T1 -= w1;
            }

            p0 = n0; p1 = n1; cb = ncb;
        }
    }

    // partials to smem (rows gw and gw+4 of the tile)
    sPart[grp][gw * 32 + glane]       = make_float4(aR0, aG0, aB0, T0);
    sPart[grp][(gw + 4) * 32 + glane] = make_float4(aR1, aG1, aB1, T1);
    __syncthreads();

    // merge in smem: out = c0 + T0*(c1 + T1*(c2 + T2*c3)); 1 px per thread
    if (tid < 256) {
        float4 s0 = sPart[0][tid];
        float4 s1 = sPart[1][tid];
        float4 s2 = sPart[2][tid];
        float4 s3 = sPart[3][tid];

        float R = fmaf(s2.w, s3.x, s2.x);
        float G = fmaf(s2.w, s3.y, s2.y);
        float B = fmaf(s2.w, s3.z, s2.z);
        R = fmaf(s1.w, R, s1.x);
        G = fmaf(s1.w, G, s1.y);
        B = fmaf(s1.w, B, s1.z);
        R = fmaf(s0.w, R, s0.x);
        G = fmaf(s0.w, G, s0.y);
        B = fmaf(s0.w, B, s0.z);

        int x = txi * 32 + (tid & 31);
        int y = tyi * 8 + (tid >> 5);
        int o = (y * IMG_W + x) * 3;
        out[o + 0] = R;
        out[o + 1] = G;
        out[o + 2] = B;
    }

    // reset sync state for the next graph replay.
    // Safe: a block increments g_fin only after all its work; the 256th
    // increment implies every render block passed the ready-line spin.
    __syncthreads();
    if (tid == 0) sLast = (atomicAdd(&g_fin, 1) == NBLK_REND - 1);
    __syncthreads();
    if (sLast) {
        if (tid < NREADY) g_ready[tid] = 0;
        if (tid == 0) {
            g_flag1 = 0;
            __threadfence();
            g_fin = 0;
        }
    }
}

extern "C" void kernel_launch(void* const* d_in, const int* in_sizes, int n_in,
                              void* d_out, int out_size) {
    const float* means3D   = (const float*)d_in[0];
    const float* covs3d    = (const float*)d_in[1];
    const float* colors    = (const float*)d_in[2];
    const float* opacities = (const float*)d_in[3];
    const float* K         = (const float*)d_in[4];
    const float* R         = (const float*)d_in[5];
    const float* t         = (const float*)d_in[6];
    float* out = (float*)d_out;

    fused_kernel<<<NBLK_TOT, 512>>>(means3D, covs3d, colors, opacities,
                                    K, R, t, out);
}

// round 15
// speedup vs baseline: 1.2003x; 1.2003x over previous
#include <cuda_runtime.h>
#include <math.h>

#define NG 512
#define NSEG 4
#define SEGSZ 128
#define IMG_H 256
#define IMG_W 256
#define NPIX (IMG_H * IMG_W)
#define NTILE 128               // 8 x 16 tiles of 32x16 px
#define EPSV 1e-4f
#define CUT 40.0f

#define NBLK_PROJ 128
#define NBLK_REND 512           // 8 x 16 tiles x 4 segments
#define NBLK_TOT  (NBLK_PROJ + NBLK_REND)
#define NREADY 64               // fan-out release lines

// Sorted-by-depth gaussian params:
//  g_cull[r] = (mx, my, rx, ry)   conservative ellipse AABB half-extents
//  g_p0[r]   = (mx, my, ia, ib)   mean + inverse-cov entries
//  g_p1[r]   = (id, coeff, colR, colG)
//  g_cb[r]   = colB
__device__ float4 g_cull[NG];
__device__ float4 g_p0[NG];
__device__ float4 g_p1[NG];
__device__ float  g_cb[NG];
// Per-segment partial composites: (R, G, B, T) per pixel, segment-major.
__device__ float4 g_seg[NSEG * NPIX];
// Sync state. Everything returns to 0 before kernel end (graph-replay safe):
//  g_flag1: projection-done counter (0 -> 128)
//  g_ready: 64 fan-out release lines (0 -> 1), polled by render blocks
//  g_done:  per-tile arrival counters (0 -> 4)
//  g_fin:   merged-tile counter (0 -> 128)
__device__ int g_flag1;
__device__ int g_ready[NREADY];
__device__ int g_done[NTILE];
__device__ int g_fin;

__device__ __forceinline__ int acq_load(const int* p) {
    int v;
    asm volatile("ld.acquire.gpu.b32 %0, [%1];" : "=r"(v) : "l"(p) : "memory");
    return v;
}

// ---------------------------------------------------------------------------
// Fused kernel: 640 blocks x 128 threads, all co-resident:
// launch_bounds(128, 6) -> <=85 regs -> 6 blocks/SM -> 888 slots >= 640,
// so every block lands in wave 1 and the ready-line spin cannot deadlock.
// No global barrier: merge is per-tile (4 arrivals), validated in R11-R13.
//   blocks [0,128):   projection + stable depth sort (1 warp / gaussian)
//   blocks [128,640): per-(32x16 tile, segment) cull + composite (4 px/thr)
//                     + per-tile merge by the 4th arriving block.
// Per-pixel composited sets are identical to the 32x8 tiling (a gaussian
// passing the bigger AABB but not the pixel's old half-tile AABB has
// m >= CUT there), so rel_err is bit-identical to R13.
// ---------------------------------------------------------------------------
__global__ void __launch_bounds__(128, 6) fused_kernel(
        const float* __restrict__ means3D,
        const float* __restrict__ covs3d,
        const float* __restrict__ colors,
        const float* __restrict__ opac,
        const float* __restrict__ Km,
        const float* __restrict__ Rm,
        const float* __restrict__ tv,
        float* __restrict__ out) {
    __shared__ __align__(16) unsigned long long skey[NG];   // projection path
    __shared__ float4 sG1[SEGSZ + 1];                        // render path
    __shared__ float4 sG2[SEGSZ + 1];                        // (+1 = sentinel)
    __shared__ float  sCB[SEGSZ + 1];
    __shared__ int segTot[4];
    __shared__ int segOff[4];
    __shared__ int sCount;
    __shared__ int sLast;

    int bid  = blockIdx.x;
    int tid  = threadIdx.x;
    int lane = tid & 31;
    int wrp  = tid >> 5;

    // ======================= PROJECTION BLOCKS =============================
    if (bid < NBLK_PROJ) {
        float R00=Rm[0],R01=Rm[1],R02=Rm[2];
        float R10=Rm[3],R11=Rm[4],R12=Rm[5];
        float R20=Rm[6],R21=Rm[7],R22=Rm[8];
        float tx0=tv[0], tx1=tv[1], tx2=tv[2];

        // phase A: all 512 depth keys (4 per thread).
        // depth >= 1 > 0 so float bit order == value order;
        // (depth_bits<<32 | idx) rank == stable jnp.argsort.
        #pragma unroll
        for (int k = 0; k < 4; k++) {
            int g = k * 128 + tid;
            float m0 = means3D[3*g], m1 = means3D[3*g+1], m2 = means3D[3*g+2];
            float cz = R20*m0 + R21*m1 + R22*m2 + tx2;
            float depth = fmaxf(cz, 1.0f);
            skey[g] = ((unsigned long long)__float_as_uint(depth) << 32) | (unsigned)g;
        }
        __syncthreads();

        // phase B: one warp per gaussian; all 32 lanes redundantly project
        // (issues the LDGs early so their latency overlaps the rank scan).
        int i = bid * 4 + wrp;

        float m0 = means3D[3*i], m1 = means3D[3*i+1], m2 = means3D[3*i+2];
        const float* C = covs3d + 9*i;
        float C0=C[0],C1=C[1],C2=C[2],C3=C[3],C4=C[4],C5=C[5],C6=C[6],C7=C[7],C8=C[8];
        float c0 = colors[3*i], c1 = colors[3*i+1], c2 = colors[3*i+2];
        float op = opac[i];

        float cx = R00*m0 + R01*m1 + R02*m2 + tx0;
        float cy = R10*m0 + R11*m1 + R12*m2 + tx1;
        float cz = R20*m0 + R21*m1 + R22*m2 + tx2;
        float z = cz;
        float depth = fmaxf(z, 1.0f);

        float K00=Km[0],K01=Km[1],K02=Km[2];
        float K10=Km[3],K11=Km[4],K12=Km[5];
        float K20=Km[6],K21=Km[7],K22=Km[8];

        float sx = K00*cx + K01*cy + K02*cz;
        float sy = K10*cx + K11*cy + K12*cz;
        float sz = K20*cx + K21*cy + K22*cz;
        float mx = sx / sz;
        float my = sy / sz;

        // C_cam = R C R^T ; need (0,0), (0,1), (1,1)
        float u0 = R00*C0 + R01*C3 + R02*C6;
        float u1 = R00*C1 + R01*C4 + R02*C7;
        float u2 = R00*C2 + R01*C5 + R02*C8;
        float v0 = R10*C0 + R11*C3 + R12*C6;
        float v1 = R10*C1 + R11*C4 + R12*C7;
        float v2 = R10*C2 + R11*C5 + R12*C8;
        float Cc00 = u0*R00 + u1*R01 + u2*R02;
        float Cc01 = u0*R10 + u1*R11 + u2*R12;
        float Cc11 = v0*R10 + v1*R11 + v2*R12;

        // only J[0,0]=fx/z, J[1,1]=fy/z survive the [:2,:2] slice of J^T C J
        float jx = K00 / z;
        float jy = K11 / z;
        float a = jx*jx*Cc00 + EPSV;
        float b = jx*jy*Cc01;
        float d = jy*jy*Cc11 + EPSV;

        float det    = a*d - b*b;
        float invdet = 1.0f / det;
        float ia =  d * invdet;
        float ib = -b * invdet;
        float id =  a * invdet;

        float norm  = 1.0f / (6.283185307179586f * sqrtf(det));
        bool  valid = (depth > 1.0f) && (depth < 50.0f);
        float coeff = valid ? (op * norm) : 0.0f;

        float rxv = valid ? sqrtf(CUT * a) : -1e30f;
        float ryv = valid ? sqrtf(CUT * d) : -1e30f;

        // warp-cooperative stable rank over ALL 512 keys:
        // 32 lanes x 8 uint4 = 256 uint4; sk4[j*32+lane] is conflict-free.
        unsigned long long ki = skey[i];
        const uint4* sk4 = (const uint4*)skey;
        int r = 0;
        #pragma unroll
        for (int j = 0; j < 8; j++) {
            uint4 v = sk4[j * 32 + lane];
            unsigned long long k0 = ((unsigned long long)v.y << 32) | v.x;
            unsigned long long k1 = ((unsigned long long)v.w << 32) | v.z;
            r += (int)(k0 < ki) + (int)(k1 < ki);
        }
        r = __reduce_add_sync(0xffffffffu, r);

        if (lane == 0) {
            g_cull[r] = make_float4(mx, my, rxv, ryv);
            g_p0[r]   = make_float4(mx, my, ia, ib);
            g_p1[r]   = make_float4(id, coeff, c0, c1);
            g_cb[r]   = c2;
        }
        __syncthreads();
        if (tid == 0) {
            __threadfence();                 // release g_* writes
            sLast = (atomicAdd(&g_flag1, 1) == NBLK_PROJ - 1);
        }
        __syncthreads();
        if (sLast) {
            __threadfence();
            if (tid < NREADY) atomicExch(&g_ready[tid], 1);   // fan-out release
        }
        return;
    }

    // ========================= RENDER BLOCKS ===============================
    int rid  = bid - NBLK_PROJ;          // 0..511
    int seg  = rid >> 7;                 // 0..3
    int txi  = rid & 7;                  // tile x (0..7)
    int tyi  = (rid >> 3) & 15;          // tile y (0..15)
    int tile = tyi * 8 + txi;

    // wait for projection on this block's ready line (8 pollers per line)
    if (tid == 0) {
        while (acq_load(&g_ready[rid & (NREADY - 1)]) == 0) __nanosleep(100);
    }
    __syncthreads();

    float x0 = (float)(txi * 32);
    float y0 = (float)(tyi * 16);
    float x1 = x0 + 31.0f;
    float y1 = y0 + 15.0f;

    // cull this segment's 128 gaussians against the 32x16 tile AABB
    int g = seg * SEGSZ + tid;
    float4 c = g_cull[g];
    bool keep = (c.x + c.z >= x0) && (c.x - c.z <= x1) &&
                (c.y + c.w >= y0) && (c.y - c.w <= y1);
    unsigned mask = __ballot_sync(0xffffffffu, keep);
    if (lane == 0) segTot[wrp] = __popc(mask);
    __syncthreads();
    if (tid == 0) {
        int s = 0;
        #pragma unroll
        for (int w = 0; w < 4; w++) { segOff[w] = s; s += segTot[w]; }
        sCount = s;
        // sentinel: far-away mean, zero coeff -> never hits, kills the clamp
        sG1[s] = make_float4(1e30f, 1e30f, 1.0f, 0.0f);
        sG2[s] = make_float4(1.0f, 0.0f, 0.0f, 0.0f);
        sCB[s] = 0.0f;
    }
    __syncthreads();

    // order-preserving scatter into smem
    if (keep) {
        int pos = segOff[wrp] + __popc(mask & ((1u << lane) - 1u));
        sG1[pos] = g_p0[g];
        sG2[pos] = g_p1[g];
        sCB[pos] = g_cb[g];
    }
    __syncthreads();
    int count = sCount;

    // 4 pixels per thread: rows wrp, wrp+4, wrp+8, wrp+12 of the tile
    int x  = txi * 32 + lane;
    int yb = tyi * 16 + wrp;
    int pix0 = (yb     ) * IMG_W + x;
    int pix1 = (yb + 4 ) * IMG_W + x;
    int pix2 = (yb + 8 ) * IMG_W + x;
    int pix3 = (yb + 12) * IMG_W + x;

    float T0 = 1.f, T1 = 1.f, T2 = 1.f, T3 = 1.f;
    float aR0=0.f,aG0=0.f,aB0=0.f, aR1=0.f,aG1=0.f,aB1=0.f;
    float aR2=0.f,aG2=0.f,aB2=0.f, aR3=0.f,aG3=0.f,aB3=0.f;

    if (count > 0) {
        float px  = x0 + (float)lane;
        float py0 = y0 + (float)wrp;

        // software-pipelined loop: prefetch i+1 (sentinel-padded, no clamp)
        float4 p0 = sG1[0], p1 = sG2[0];
        float  cb = sCB[0];

        for (int i = 0; i < count; i++) {
            float4 n0 = sG1[i + 1];
            float4 n1 = sG2[i + 1];
            float  ncb = sCB[i + 1];

            float dx  = px - p0.x;
            float dy0 = py0         - p0.y;
            float dy1 = py0 + 4.0f  - p0.y;
            float dy2 = py0 + 8.0f  - p0.y;
            float dy3 = py0 + 12.0f - p0.y;

            // m = ia*dx^2 + 2*ib*dx*dy + id*dy^2, shared A/B across rows
            float A = p0.z * dx * dx;           // ia*dx^2
            float B = 2.0f * p0.w * dx;         // 2*ib*dx
            float m0 = fmaf(dy0, fmaf(p1.x, dy0, B), A);
            float m1 = fmaf(dy1, fmaf(p1.x, dy1, B), A);
            float m2 = fmaf(dy2, fmaf(p1.x, dy2, B), A);
            float m3 = fmaf(dy3, fmaf(p1.x, dy3, B), A);

            float mmin = fminf(fminf(m0, m1), fminf(m2, m3));
            if (mmin < CUT) {
                float e0 = p1.y * __expf(-0.5f * m0);
                float e1 = p1.y * __expf(-0.5f * m1);
                float e2 = p1.y * __expf(-0.5f * m2);
                float e3 = p1.y * __expf(-0.5f * m3);
                float w0 = e0 * T0, w1 = e1 * T1, w2 = e2 * T2, w3 = e3 * T3;
                aR0 = fmaf(w0, p1.z, aR0); aG0 = fmaf(w0, p1.w, aG0); aB0 = fmaf(w0, cb, aB0);
                aR1 = fmaf(w1, p1.z, aR1); aG1 = fmaf(w1, p1.w, aG1); aB1 = fmaf(w1, cb, aB1);
                aR2 = fmaf(w2, p1.z, aR2); aG2 = fmaf(w2, p1.w, aG2); aB2 = fmaf(w2, cb, aB2);
                aR3 = fmaf(w3, p1.z, aR3); aG3 = fmaf(w3, p1.w, aG3); aB3 = fmaf(w3, cb, aB3);
                T0 -= w0; T1 -= w1; T2 -= w2; T3 -= w3;
            }

            p0 = n0; p1 = n1; cb = ncb;
        }
    }

    // publish this segment's partials
    g_seg[seg * NPIX + pix0] = make_float4(aR0, aG0, aB0, T0);
    g_seg[seg * NPIX + pix1] = make_float4(aR1, aG1, aB1, T1);
    g_seg[seg * NPIX + pix2] = make_float4(aR2, aG2, aB2, T2);
    g_seg[seg * NPIX + pix3] = make_float4(aR3, aG3, aB3, T3);

    // arrive at the tile counter; 4th block merges
    __threadfence();          // release partials
    __syncthreads();          // all threads' stores included before arrive
    if (tid == 0) sLast = (atomicAdd(&g_done[tile], 1) == NSEG - 1);
    __syncthreads();
    if (!sLast) return;
    __threadfence();          // acquire other blocks' partials

    // merge: out = c0 + T0*(c1 + T1*(c2 + T2*c3)); own segment from registers.
    float4 ownP[4] = { make_float4(aR0, aG0, aB0, T0),
                       make_float4(aR1, aG1, aB1, T1),
                       make_float4(aR2, aG2, aB2, T2),
                       make_float4(aR3, aG3, aB3, T3) };
    int pixv[4] = { pix0, pix1, pix2, pix3 };

    #pragma unroll
    for (int h = 0; h < 4; h++) {
        int pix = pixv[h];
        float4 own = ownP[h];

        float4 s0 = (seg == 0) ? own : g_seg[pix];
        float4 s1 = (seg == 1) ? own : g_seg[pix + NPIX];
        float4 s2 = (seg == 2) ? own : g_seg[pix + 2 * NPIX];
        float4 s3 = (seg == 3) ? own : g_seg[pix + 3 * NPIX];

        float R = fmaf(s2.w, s3.x, s2.x);
        float G = fmaf(s2.w, s3.y, s2.y);
        float B = fmaf(s2.w, s3.z, s2.z);
        R = fmaf(s1.w, R, s1.x);
        G = fmaf(s1.w, G, s1.y);
        B = fmaf(s1.w, B, s1.z);
        R = fmaf(s0.w, R, s0.x);
        G = fmaf(s0.w, G, s0.y);
        B = fmaf(s0.w, B, s0.z);

        int o = pix * 3;
        out[o + 0] = R;
        out[o + 1] = G;
        out[o + 2] = B;
    }

    // reset all sync state for the next graph replay.
    // Safe: the 128th merged tile implies all 512 render blocks passed the
    // ready-line spin, so nobody can still be polling g_ready/g_flag1.
    __syncthreads();
    if (tid == 0) {
        g_done[tile] = 0;
        sLast = (atomicAdd(&g_fin, 1) == NTILE - 1);
    }
    __syncthreads();
    if (sLast) {
        if (tid < NREADY) g_ready[tid] = 0;
        if (tid == 0) {
            g_flag1 = 0;
            __threadfence();
            g_fin = 0;
        }
    }
}

extern "C" void kernel_launch(void* const* d_in, const int* in_sizes, int n_in,
                              void* d_out, int out_size) {
    const float* means3D   = (const float*)d_in[0];
    const float* covs3d    = (const float*)d_in[1];
    const float* colors    = (const float*)d_in[2];
    const float* opacities = (const float*)d_in[3];
    const float* K         = (const float*)d_in[4];
    const float* R         = (const float*)d_in[5];
    const float* t         = (const float*)d_in[6];
    float* out = (float*)d_out;

    fused_kernel<<<NBLK_TOT, 128>>>(means3D, covs3d, colors, opacities,
                                    K, R, t, out);
}

// round 16
// speedup vs baseline: 1.3592x; 1.1323x over previous
#include <cuda_runtime.h>
#include <math.h>

#define NG 512
#define NSEG 4
#define SEGSZ 128
#define IMG_H 256
#define IMG_W 256
#define NPIX (IMG_H * IMG_W)
#define NTILE 256               // 8 x 32 tiles of 32x8 px
#define EPSV 1e-4f
#define CUT 40.0f

#define NBLK_PROJ 128
#define NBLK_REND 1024          // 8 x 32 tiles x 4 segments
#define NBLK_TOT  (NBLK_PROJ + NBLK_REND)
#define NREADY 64               // fan-out release lines

// Sorted-by-depth gaussian params (repacked: mean lives only in g_cull):
//  g_cull[r] = (mx, my, rx, ry)   mean + conservative ellipse half-extents
//  g_pA[r]   = (ia, ib, id, coeff)
//  g_pB[r]   = (colR, colG, colB, 0)
__device__ float4 g_cull[NG];
__device__ float4 g_pA[NG];
__device__ float4 g_pB[NG];
// Per-segment partial composites: (R, G, B, T) per pixel, segment-major.
__device__ float4 g_seg[NSEG * NPIX];
// Sync state. Everything returns to 0 before kernel end (graph-replay safe):
//  g_flag1: projection-done counter (0 -> 128)
//  g_ready: 64 fan-out release lines (0 -> 1), polled by render blocks
//  g_done:  per-tile arrival counters (0 -> 4)
//  g_fin:   merged-tile counter (0 -> 256)
__device__ int g_flag1;
__device__ int g_ready[NREADY];
__device__ int g_done[NTILE];
__device__ int g_fin;

__device__ __forceinline__ int acq_load(const int* p) {
    int v;
    asm volatile("ld.acquire.gpu.b32 %0, [%1];" : "=r"(v) : "l"(p) : "memory");
    return v;
}

// ---------------------------------------------------------------------------
// Fused kernel: 1152 blocks x 128 threads, all co-resident:
// launch_bounds(128, 8) -> <=64 regs -> 8 blocks/SM -> 1184 slots >= 1152,
// static smem ~9 KB/block, so every block lands in wave 1 and the ready-line
// spin cannot deadlock. No global barrier: merge is per-tile (4 arrivals).
//   blocks [0,128):     projection + stable depth sort (1 warp / gaussian)
//   blocks [128,1152):  per-(tile,segment) cull + composite + per-tile merge
// R16 deltas vs R13 (structure identical): all param LDGs issued together
// with the cull load (one L2 round-trip removed from each block's serial
// chain); 3 packed float4 loads instead of 4; spin fast-path.
// ---------------------------------------------------------------------------
__global__ void __launch_bounds__(128, 8) fused_kernel(
        const float* __restrict__ means3D,
        const float* __restrict__ covs3d,
        const float* __restrict__ colors,
        const float* __restrict__ opac,
        const float* __restrict__ Km,
        const float* __restrict__ Rm,
        const float* __restrict__ tv,
        float* __restrict__ out) {
    __shared__ __align__(16) unsigned long long skey[NG];   // projection path
    __shared__ float4 sG1[SEGSZ + 1];                        // render path
    __shared__ float4 sG2[SEGSZ + 1];                        // (+1 = sentinel)
    __shared__ float  sCB[SEGSZ + 1];
    __shared__ int segTot[4];
    __shared__ int segOff[4];
    __shared__ int sCount;
    __shared__ int sLast;

    int bid  = blockIdx.x;
    int tid  = threadIdx.x;
    int lane = tid & 31;
    int wrp  = tid >> 5;

    // ======================= PROJECTION BLOCKS =============================
    if (bid < NBLK_PROJ) {
        float R00=Rm[0],R01=Rm[1],R02=Rm[2];
        float R10=Rm[3],R11=Rm[4],R12=Rm[5];
        float R20=Rm[6],R21=Rm[7],R22=Rm[8];
        float tx0=tv[0], tx1=tv[1], tx2=tv[2];

        // phase A: all 512 depth keys (4 per thread).
        // depth >= 1 > 0 so float bit order == value order;
        // (depth_bits<<32 | idx) rank == stable jnp.argsort.
        #pragma unroll
        for (int k = 0; k < 4; k++) {
            int g = k * 128 + tid;
            float m0 = means3D[3*g], m1 = means3D[3*g+1], m2 = means3D[3*g+2];
            float cz = R20*m0 + R21*m1 + R22*m2 + tx2;
            float depth = fmaxf(cz, 1.0f);
            skey[g] = ((unsigned long long)__float_as_uint(depth) << 32) | (unsigned)g;
        }
        __syncthreads();

        // phase B: one warp per gaussian; all 32 lanes redundantly project
        // (issues the LDGs early so their latency overlaps the rank scan).
        int i = bid * 4 + wrp;

        float m0 = means3D[3*i], m1 = means3D[3*i+1], m2 = means3D[3*i+2];
        const float* C = covs3d + 9*i;
        float C0=C[0],C1=C[1],C2=C[2],C3=C[3],C4=C[4],C5=C[5],C6=C[6],C7=C[7],C8=C[8];
        float c0 = colors[3*i], c1 = colors[3*i+1], c2 = colors[3*i+2];
        float op = opac[i];

        float cx = R00*m0 + R01*m1 + R02*m2 + tx0;
        float cy = R10*m0 + R11*m1 + R12*m2 + tx1;
        float cz = R20*m0 + R21*m1 + R22*m2 + tx2;
        float z = cz;
        float depth = fmaxf(z, 1.0f);

        float K00=Km[0],K01=Km[1],K02=Km[2];
        float K10=Km[3],K11=Km[4],K12=Km[5];
        float K20=Km[6],K21=Km[7],K22=Km[8];

        float sx = K00*cx + K01*cy + K02*cz;
        float sy = K10*cx + K11*cy + K12*cz;
        float sz = K20*cx + K21*cy + K22*cz;
        float mx = sx / sz;
        float my = sy / sz;

        // C_cam = R C R^T ; need (0,0), (0,1), (1,1)
        float u0 = R00*C0 + R01*C3 + R02*C6;
        float u1 = R00*C1 + R01*C4 + R02*C7;
        float u2 = R00*C2 + R01*C5 + R02*C8;
        float v0 = R10*C0 + R11*C3 + R12*C6;
        float v1 = R10*C1 + R11*C4 + R12*C7;
        float v2 = R10*C2 + R11*C5 + R12*C8;
        float Cc00 = u0*R00 + u1*R01 + u2*R02;
        float Cc01 = u0*R10 + u1*R11 + u2*R12;
        float Cc11 = v0*R10 + v1*R11 + v2*R12;

        // only J[0,0]=fx/z, J[1,1]=fy/z survive the [:2,:2] slice of J^T C J
        float jx = K00 / z;
        float jy = K11 / z;
        float a = jx*jx*Cc00 + EPSV;
        float b = jx*jy*Cc01;
        float d = jy*jy*Cc11 + EPSV;

        float det    = a*d - b*b;
        float invdet = 1.0f / det;
        float ia =  d * invdet;
        float ib = -b * invdet;
        float id =  a * invdet;

        float norm  = 1.0f / (6.283185307179586f * sqrtf(det));
        bool  valid = (depth > 1.0f) && (depth < 50.0f);
        float coeff = valid ? (op * norm) : 0.0f;

        float rxv = valid ? sqrtf(CUT * a) : -1e30f;
        float ryv = valid ? sqrtf(CUT * d) : -1e30f;

        // warp-cooperative stable rank over ALL 512 keys:
        // 32 lanes x 8 uint4 = 256 uint4; sk4[j*32+lane] is conflict-free.
        unsigned long long ki = skey[i];
        const uint4* sk4 = (const uint4*)skey;
        int r = 0;
        #pragma unroll
        for (int j = 0; j < 8; j++) {
            uint4 v = sk4[j * 32 + lane];
            unsigned long long k0 = ((unsigned long long)v.y << 32) | v.x;
            unsigned long long k1 = ((unsigned long long)v.w << 32) | v.z;
            r += (int)(k0 < ki) + (int)(k1 < ki);
        }
        r = __reduce_add_sync(0xffffffffu, r);

        if (lane == 0) {
            g_cull[r] = make_float4(mx, my, rxv, ryv);
            g_pA[r]   = make_float4(ia, ib, id, coeff);
            g_pB[r]   = make_float4(c0, c1, c2, 0.0f);
        }
        __syncthreads();
        if (tid == 0) {
            __threadfence();                 // release g_* writes
            sLast = (atomicAdd(&g_flag1, 1) == NBLK_PROJ - 1);
        }
        __syncthreads();
        if (sLast) {
            __threadfence();
            if (tid < NREADY) atomicExch(&g_ready[tid], 1);   // fan-out release
        }
        return;
    }

    // ========================= RENDER BLOCKS ===============================
    int rid  = bid - NBLK_PROJ;
    int seg  = rid >> 8;                 // 0..3
    int txi  = rid & 7;                  // tile x (0..7)
    int tyi  = (rid >> 3) & 31;          // tile y (0..31)
    int tile = tyi * 8 + txi;

    // wait for projection (fast-path check, then 64ns backoff; 16 pollers/line)
    if (tid == 0) {
        const int* line = &g_ready[rid & (NREADY - 1)];
        if (acq_load(line) == 0) {
            do { __nanosleep(64); } while (acq_load(line) == 0);
        }
    }
    __syncthreads();

    float x0 = (float)(txi * 32);
    float y0 = (float)(tyi * 8);
    float x1 = x0 + 31.0f;
    float y1 = y0 + 7.0f;

    // issue ALL loads for this thread's gaussian back-to-back (one L2
    // round-trip instead of two serialized ones), then cull
    int g = seg * SEGSZ + tid;
    float4 c  = g_cull[g];
    float4 pA = g_pA[g];
    float4 pB = g_pB[g];

    bool keep = (c.x + c.z >= x0) && (c.x - c.z <= x1) &&
                (c.y + c.w >= y0) && (c.y - c.w <= y1);
    unsigned mask = __ballot_sync(0xffffffffu, keep);
    if (lane == 0) segTot[wrp] = __popc(mask);
    __syncthreads();
    if (tid == 0) {
        int s = 0;
        #pragma unroll
        for (int w = 0; w < 4; w++) { segOff[w] = s; s += segTot[w]; }
        sCount = s;
        // sentinel: far-away mean, zero coeff -> never hits, kills the clamp
        sG1[s] = make_float4(1e30f, 1e30f, 1.0f, 0.0f);
        sG2[s] = make_float4(1.0f, 0.0f, 0.0f, 0.0f);
        sCB[s] = 0.0f;
    }
    __syncthreads();

    // order-preserving scatter into smem, straight from registers
    if (keep) {
        int pos = segOff[wrp] + __popc(mask & ((1u << lane) - 1u));
        sG1[pos] = make_float4(c.x, c.y, pA.x, pA.y);   // mx, my, ia, ib
        sG2[pos] = make_float4(pA.z, pA.w, pB.x, pB.y); // id, coeff, cR, cG
        sCB[pos] = pB.z;                                 // cB
    }
    __syncthreads();
    int count = sCount;

    int x  = txi * 32 + lane;
    int yA = tyi * 8 + wrp;
    int yB = yA + 4;
    int pixA = yA * IMG_W + x;
    int pixB = yB * IMG_W + x;

    float T0 = 1.0f, T1 = 1.0f;
    float aR0 = 0.f, aG0 = 0.f, aB0 = 0.f;
    float aR1 = 0.f, aG1 = 0.f, aB1 = 0.f;

    if (count > 0) {
        float px  = x0 + (float)lane;
        float py0 = y0 + (float)wrp;
        float py1 = py0 + 4.0f;

        // software-pipelined loop: prefetch i+1 (sentinel-padded, no clamp)
        float4 p0 = sG1[0], p1 = sG2[0];
        float  cb = sCB[0];

        for (int i = 0; i < count; i++) {
            float4 n0 = sG1[i + 1];
            float4 n1 = sG2[i + 1];
            float  ncb = sCB[i + 1];

            float dx  = px  - p0.x;
            float dy0 = py0 - p0.y;
            float dy1 = py1 - p0.y;
            float tx  = fmaf(p0.z, dx, p0.w * dy0);
            float ty  = fmaf(p0.w, dx, p1.x * dy0);
            float m0  = fmaf(tx, dx, ty * dy0);
            float ux  = fmaf(p0.z, dx, p0.w * dy1);
            float uy  = fmaf(p0.w, dx, p1.x * dy1);
            float m1  = fmaf(ux, dx, uy * dy1);

            if (fminf(m0, m1) < CUT) {
                float e0 = p1.y * __expf(-0.5f * m0);
                float e1 = p1.y * __expf(-0.5f * m1);
                float w0 = e0 * T0;
                float w1 = e1 * T1;
                aR0 = fmaf(w0, p1.z, aR0);
                aG0 = fmaf(w0, p1.w, aG0);
                aB0 = fmaf(w0, cb,   aB0);
                aR1 = fmaf(w1, p1.z, aR1);
                aG1 = fmaf(w1, p1.w, aG1);
                aB1 = fmaf(w1, cb,   aB1);
                T0 -= w0;
                T1 -= w1;
            }

            p0 = n0; p1 = n1; cb = ncb;
        }
    }

    // publish this segment's partial
    g_seg[seg * NPIX + pixA] = make_float4(aR0, aG0, aB0, T0);
    g_seg[seg * NPIX + pixB] = make_float4(aR1, aG1, aB1, T1);

    // arrive at the tile counter; 4th block merges
    __threadfence();          // release partials
    __syncthreads();          // all threads' stores included before arrive
    if (tid == 0) sLast = (atomicAdd(&g_done[tile], 1) == NSEG - 1);
    __syncthreads();
    if (!sLast) return;
    __threadfence();          // acquire other blocks' partials

    // merge: out = c0 + T0*(c1 + T1*(c2 + T2*c3)); own segment from registers.
    float4 own0 = make_float4(aR0, aG0, aB0, T0);
    float4 own1 = make_float4(aR1, aG1, aB1, T1);

    #pragma unroll
    for (int h = 0; h < 2; h++) {
        int pix = h ? pixB : pixA;
        float4 own = h ? own1 : own0;

        float4 s0 = (seg == 0) ? own : g_seg[pix];
        float4 s1 = (seg == 1) ? own : g_seg[pix + NPIX];
        float4 s2 = (seg == 2) ? own : g_seg[pix + 2 * NPIX];
        float4 s3 = (seg == 3) ? own : g_seg[pix + 3 * NPIX];

        float R = fmaf(s2.w, s3.x, s2.x);
        float G = fmaf(s2.w, s3.y, s2.y);
        float B = fmaf(s2.w, s3.z, s2.z);
        R = fmaf(s1.w, R, s1.x);
        G = fmaf(s1.w, G, s1.y);
        B = fmaf(s1.w, B, s1.z);
        R = fmaf(s0.w, R, s0.x);
        G = fmaf(s0.w, G, s0.y);
        B = fmaf(s0.w, B, s0.z);

        int o = pix * 3;
        out[o + 0] = R;
        out[o + 1] = G;
        out[o + 2] = B;
    }

    // reset all sync state for the next graph replay.
    // Safe: the 256th merged tile implies all 1024 render blocks have passed
    // the ready-line spin, so nobody can still be polling g_ready/g_flag1.
    __syncthreads();
    if (tid == 0) {
        g_done[tile] = 0;
        sLast = (atomicAdd(&g_fin, 1) == NTILE - 1);
    }
    __syncthreads();
    if (sLast) {
        if (tid < NREADY) g_ready[tid] = 0;
        if (tid == 0) {
            g_flag1 = 0;
            __threadfence();
            g_fin = 0;
        }
    }
}

extern "C" void kernel_launch(void* const* d_in, const int* in_sizes, int n_in,
                              void* d_out, int out_size) {
    const float* means3D   = (const float*)d_in[0];
    const float* covs3d    = (const float*)d_in[1];
    const float* colors    = (const float*)d_in[2];
    const float* opacities = (const float*)d_in[3];
    const float* K         = (const float*)d_in[4];
    const float* R         = (const float*)d_in[5];
    const float* t         = (const float*)d_in[6];
    float* out = (float*)d_out;

    fused_kernel<<<NBLK_TOT, 128>>>(means3D, covs3d, colors, opacities,
                                    K, R, t, out);
}